// round 7
// baseline (speedup 1.0000x reference)
#include <cuda_runtime.h>

// SVConvTranspose2d, round 7: scatter-in-w + N split across twin warps.
//
// x:      (4, 16, 128, 128) f32        -- 4 MB, L2-hot
// weight: (16, 16, 5, 5, 128, 128) f32 -- 419 MB, DRAM-read once
//                                         (twin np-warps dedup in L1/L2)
// bias:   (1, 16, 1, 1) f32
// out:    (4, 16, 128, 128) f32
//
// out[n,o,oh,ow] = bias[o] + sum wt[i,o,kh,kw,h,w] * x[n,i,h,w],
//   h = oh+2-kh (gather), ow = w+kw-2 (scatter into acc window).
//
// Thread owns input quad w in [4q,4q+4), 2 batches, 1 out channel, 8 input
// channels. Accumulator window acc[2][8] over out positions [4q-2,4q+6):
// tap (kw,j) -> window index j+kw. Hot loop is shuffle/mask-free: per
// (kh,ii) just 5 weight LDG.128 + 2 x LDG.128 + 40 FMA. Cross-lane combine
// (4 shuffles per batch) happens once at the end.
//
// Block = 256 thr = (ih:2 i-slices of 8) x (np:2 batch-pairs) x (o2:2 outs)
//                   x (q:32 quads).  Warp == one row of quads (q = lane).
// Grid  = 128 rows x 8 o-pairs = 1024 blocks.
// __launch_bounds__(256,5): 48-reg cap -> 40 warps/SM (62.5% occ), ~42 live
// regs so no spills. Smem: 8 KB reduce buffer over the 2 i-slices.

#define H_  128
#define W_  128
#define HW  16384

__global__ __launch_bounds__(256, 5)
void svct_kernel(const float* __restrict__ x,
                 const float* __restrict__ wt,
                 const float* __restrict__ bias,
                 float* __restrict__ out)
{
    __shared__ float red[2][2][2][2][W_];   // [o2][np][m][ih][w]  8 KB

    const int t   = threadIdx.x;
    const int q   = t & 31;              // quad index in row == lane
    const int o2  = (t >> 5) & 1;        // which of the 2 outs
    const int np  = (t >> 6) & 1;        // batch pair: n in {2np, 2np+1}
    const int ih  = (t >> 7) & 1;        // i-slice of 8
    const int oh  = blockIdx.x >> 3;     // output row
    const int og  = blockIdx.x & 7;      // o-pair
    const int oc  = og * 2 + o2;         // output channel
    const int n0  = np * 2;
    const int ibase = ih * 8;

    float acc[2][8];                     // [m][window k]
    #pragma unroll
    for (int m = 0; m < 2; m++)
        #pragma unroll
        for (int k = 0; k < 8; k++)
            acc[m][k] = 0.0f;

    #pragma unroll 1
    for (int kh = 0; kh < 5; kh++) {
        const int h = oh + 2 - kh;
        if ((unsigned)h >= (unsigned)H_) continue;

        #pragma unroll 2
        for (int ii = 0; ii < 8; ii++) {
            const int i = ibase + ii;

            // 2 L2-hot x quads, issued first so they're ready for the FMAs
            float4 xq[2];
            #pragma unroll
            for (int m = 0; m < 2; m++)
                xq[m] = __ldg((const float4*)x + (((n0 + m) * 16 + i) * H_ + h) * 32 + q);

            // 5 aligned weight quads (DRAM stream; twin np-warp dedups)
            const long wrow = ((long)((i * 16 + oc) * 5 + kh) * 5) * HW + (long)h * W_;

            #pragma unroll
            for (int kw = 0; kw < 5; kw++) {
                float4 w4 = __ldg((const float4*)(wt + wrow + (long)kw * HW) + q);
                const float wv[4] = {w4.x, w4.y, w4.z, w4.w};
                #pragma unroll
                for (int m = 0; m < 2; m++) {
                    const float xv[4] = {xq[m].x, xq[m].y, xq[m].z, xq[m].w};
                    #pragma unroll
                    for (int j = 0; j < 4; j++)
                        acc[m][j + kw] = fmaf(wv[j], xv[j], acc[m][j + kw]);
                }
            }
        }
    }

    // cross-lane combine (4 shuffles per m), then smem-reduce the i-slices
    const bool q0  = (q == 0);
    const bool q31 = (q == 31);
    #pragma unroll
    for (int m = 0; m < 2; m++) {
        float up6 = __shfl_up_sync(0xffffffffu, acc[m][6], 1);
        float up7 = __shfl_up_sync(0xffffffffu, acc[m][7], 1);
        float dn0 = __shfl_down_sync(0xffffffffu, acc[m][0], 1);
        float dn1 = __shfl_down_sync(0xffffffffu, acc[m][1], 1);
        if (q0)  { up6 = 0.0f; up7 = 0.0f; }
        if (q31) { dn0 = 0.0f; dn1 = 0.0f; }
        *(float4*)&red[o2][np][m][ih][4 * q] =
            make_float4(acc[m][2] + up6, acc[m][3] + up7,
                        acc[m][4] + dn0, acc[m][5] + dn1);
    }
    __syncthreads();

    // 256 writer threads: (o2w:2) x (nw:4) x (qw:32)
    const int o2w = t >> 7;
    const int nw  = (t >> 5) & 3;
    const int qw  = t & 31;
    const int ocw = og * 2 + o2w;

    float4 s0 = *(const float4*)&red[o2w][nw >> 1][nw & 1][0][4 * qw];
    float4 s1 = *(const float4*)&red[o2w][nw >> 1][nw & 1][1][4 * qw];

    const float b = __ldg(bias + ocw);
    float4 r;
    r.x = s0.x + s1.x + b;
    r.y = s0.y + s1.y + b;
    r.z = s0.z + s1.z + b;
    r.w = s0.w + s1.w + b;

    ((float4*)out)[((nw * 16 + ocw) * H_ + oh) * 32 + qw] = r;
}

extern "C" void kernel_launch(void* const* d_in, const int* in_sizes, int n_in,
                              void* d_out, int out_size)
{
    const float* x    = (const float*)d_in[0];
    const float* wt   = (const float*)d_in[1];
    const float* bias = (const float*)d_in[2];
    float*       out  = (float*)d_out;

    svct_kernel<<<1024, 256>>>(x, wt, bias, out);
}

// round 8
// speedup vs baseline: 1.5229x; 1.5229x over previous
#include <cuda_runtime.h>

// SVConvTranspose2d, round 8: scatter-in-w, N split across twin warps
// (L1/L2 dedups the duplicated weight reads -- verified in round 7),
// with the 5-quad weight batch RESTORED (round 7 lost it and collapsed).
//
// x:      (4, 16, 128, 128) f32        -- 4 MB, L2-hot
// weight: (16, 16, 5, 5, 128, 128) f32 -- 419 MB DRAM-read once
// bias:   (1, 16, 1, 1) f32
// out:    (4, 16, 128, 128) f32
//
// out[n,o,oh,ow] = bias[o] + sum wt[i,o,kh,kw,h,w] * x[n,i,h,w],
//   h = oh+2-kh (gather), ow = w+kw-2 (scatter into acc window).
//
// Thread: input quad w in [4q,4q+4), 2 batches, 1 out channel, 8 input
// channels. acc[2][8] window over out positions [4q-2,4q+6): tap (kw,j)
// -> index j+kw. Hot loop per (kh,ii): 5 weight LDG.128 batched FIRST,
// then 2 x LDG.128, then 40 FMA. No shuffles/masks in the loop.
//
// Block = 256 thr = (ih:2 i-slices of 8) x (np:2 batch-pairs) x (o2:2 outs)
//                   x (q:32 quads). Twin np-warps share weight lines in L1.
// Grid  = 128 rows x 8 o-pairs = 1024 blocks.
// __launch_bounds__(256,4): 64-reg cap, ~54 live regs -> no spill, 32
// warps/SM (50% occ) with a 5-deep weight batch per warp.

#define H_  128
#define W_  128
#define HW  16384

__global__ __launch_bounds__(256, 4)
void svct_kernel(const float* __restrict__ x,
                 const float* __restrict__ wt,
                 const float* __restrict__ bias,
                 float* __restrict__ out)
{
    __shared__ float red[2][2][2][2][W_];   // [o2][np][m][ih][w]  8 KB

    const int t   = threadIdx.x;
    const int q   = t & 31;              // quad index in row == lane
    const int o2  = (t >> 5) & 1;        // which of the 2 outs
    const int np  = (t >> 6) & 1;        // batch pair: n in {2np, 2np+1}
    const int ih  = (t >> 7) & 1;        // i-slice of 8
    const int oh  = blockIdx.x >> 3;     // output row
    const int og  = blockIdx.x & 7;      // o-pair
    const int oc  = og * 2 + o2;         // output channel
    const int n0  = np * 2;
    const int ibase = ih * 8;

    float acc[2][8];                     // [m][window k]
    #pragma unroll
    for (int m = 0; m < 2; m++)
        #pragma unroll
        for (int k = 0; k < 8; k++)
            acc[m][k] = 0.0f;

    #pragma unroll 1
    for (int kh = 0; kh < 5; kh++) {
        const int h = oh + 2 - kh;
        if ((unsigned)h >= (unsigned)H_) continue;

        #pragma unroll 1
        for (int ii = 0; ii < 8; ii++) {
            const int i = ibase + ii;

            // Weight batch FIRST: 5 aligned quads, 5 independent DRAM lines
            // in flight per warp. __ldg so the twin np-warp hits L1.
            const long wrow = ((long)((i * 16 + oc) * 5 + kh) * 5) * HW + (long)h * W_;
            float4 w4[5];
            #pragma unroll
            for (int kw = 0; kw < 5; kw++)
                w4[kw] = __ldg((const float4*)(wt + wrow + (long)kw * HW) + q);

            // Then 2 L2-hot x quads at the same spatial position.
            float4 xq[2];
            #pragma unroll
            for (int m = 0; m < 2; m++)
                xq[m] = __ldg((const float4*)x + (((n0 + m) * 16 + i) * H_ + h) * 32 + q);

            #pragma unroll
            for (int kw = 0; kw < 5; kw++) {
                const float wv[4] = {w4[kw].x, w4[kw].y, w4[kw].z, w4[kw].w};
                #pragma unroll
                for (int m = 0; m < 2; m++) {
                    const float xv[4] = {xq[m].x, xq[m].y, xq[m].z, xq[m].w};
                    #pragma unroll
                    for (int j = 0; j < 4; j++)
                        acc[m][j + kw] = fmaf(wv[j], xv[j], acc[m][j + kw]);
                }
            }
        }
    }

    // cross-lane combine (4 shuffles per m), then smem-reduce the i-slices
    const bool q0  = (q == 0);
    const bool q31 = (q == 31);
    #pragma unroll
    for (int m = 0; m < 2; m++) {
        float up6 = __shfl_up_sync(0xffffffffu, acc[m][6], 1);
        float up7 = __shfl_up_sync(0xffffffffu, acc[m][7], 1);
        float dn0 = __shfl_down_sync(0xffffffffu, acc[m][0], 1);
        float dn1 = __shfl_down_sync(0xffffffffu, acc[m][1], 1);
        if (q0)  { up6 = 0.0f; up7 = 0.0f; }
        if (q31) { dn0 = 0.0f; dn1 = 0.0f; }
        *(float4*)&red[o2][np][m][ih][4 * q] =
            make_float4(acc[m][2] + up6, acc[m][3] + up7,
                        acc[m][4] + dn0, acc[m][5] + dn1);
    }
    __syncthreads();

    // 256 writer threads: (o2w:2) x (nw:4) x (qw:32)
    const int o2w = t >> 7;
    const int nw  = (t >> 5) & 3;
    const int qw  = t & 31;
    const int ocw = og * 2 + o2w;

    float4 s0 = *(const float4*)&red[o2w][nw >> 1][nw & 1][0][4 * qw];
    float4 s1 = *(const float4*)&red[o2w][nw >> 1][nw & 1][1][4 * qw];

    const float b = __ldg(bias + ocw);
    float4 r;
    r.x = s0.x + s1.x + b;
    r.y = s0.y + s1.y + b;
    r.z = s0.z + s1.z + b;
    r.w = s0.w + s1.w + b;

    ((float4*)out)[((nw * 16 + ocw) * H_ + oh) * 32 + qw] = r;
}

extern "C" void kernel_launch(void* const* d_in, const int* in_sizes, int n_in,
                              void* d_out, int out_size)
{
    const float* x    = (const float*)d_in[0];
    const float* wt   = (const float*)d_in[1];
    const float* bias = (const float*)d_in[2];
    float*       out  = (float*)d_out;

    svct_kernel<<<1024, 256>>>(x, wt, bias, out);
}